// round 3
// baseline (speedup 1.0000x reference)
#include <cuda_runtime.h>
#include <cstdint>

#define BB 4
#define SS 2048
#define HH 1024
#define NHH 16
#define HDD 64
#define BH (BB*NHH)   // 64 heads total

// Scratch: Q,K head-major [B*NH][S][HD]; V transposed [B*NH][HD][S]
__device__ float g_q[BB*SS*HH];
__device__ float g_k[BB*SS*HH];
__device__ float g_v[BB*SS*HH];

__device__ __forceinline__ float tf32r(float x) {
    uint32_t r;
    asm("cvt.rna.tf32.f32 %0, %1;" : "=r"(r) : "f"(x));
    return __uint_as_float(r);
}
__device__ __forceinline__ uint32_t fb(float x) { return __float_as_uint(x); }

__device__ __forceinline__ void mma8(float c[4],
                                     uint32_t a0, uint32_t a1, uint32_t a2, uint32_t a3,
                                     uint32_t b0, uint32_t b1) {
    asm volatile(
        "mma.sync.aligned.m16n8k8.row.col.f32.tf32.tf32.f32 "
        "{%0,%1,%2,%3},{%4,%5,%6,%7},{%8,%9},{%0,%1,%2,%3};\n"
        : "+f"(c[0]), "+f"(c[1]), "+f"(c[2]), "+f"(c[3])
        : "r"(a0), "r"(a1), "r"(a2), "r"(a3), "r"(b0), "r"(b1));
}

// ======================= QKV projection GEMM =======================
// (unchanged from R2)
__global__ __launch_bounds__(256) void qkv_gemm_kernel(
    const float* __restrict__ X,
    const float* __restrict__ Wq, const float* __restrict__ bq,
    const float* __restrict__ Wk, const float* __restrict__ bk,
    const float* __restrict__ Wv, const float* __restrict__ bv)
{
    __shared__ float As[128 * 36];
    __shared__ float Bs[128 * 36];

    const float* W; const float* bias; float* out;
    if (blockIdx.z == 0)      { W = Wq; bias = bq; out = g_q; }
    else if (blockIdx.z == 1) { W = Wk; bias = bk; out = g_k; }
    else                      { W = Wv; bias = bv; out = g_v; }
    const bool vtrans = (blockIdx.z == 2);

    const int m0 = blockIdx.x * 128;
    const int n0 = blockIdx.y * 128;
    const int tid = threadIdx.x;
    const int lane = tid & 31, warp = tid >> 5;
    const int wm = warp >> 2, wn = warp & 3;
    const int g = lane >> 2, tg = lane & 3;

    float acc[4][4][4];
    #pragma unroll
    for (int mt = 0; mt < 4; mt++)
        #pragma unroll
        for (int nt = 0; nt < 4; nt++)
            #pragma unroll
            for (int j = 0; j < 4; j++) acc[mt][nt][j] = 0.f;

    for (int k0 = 0; k0 < HH; k0 += 32) {
        #pragma unroll
        for (int i = 0; i < 4; i++) {
            int idx = tid + i * 256;
            int row = idx >> 3;
            int c4  = (idx & 7) * 4;
            float4 va = *(const float4*)&X[(size_t)(m0 + row) * HH + k0 + c4];
            float4 ta = make_float4(tf32r(va.x), tf32r(va.y), tf32r(va.z), tf32r(va.w));
            *(float4*)&As[row * 36 + c4] = ta;
            float4 vb = *(const float4*)&W[(size_t)(n0 + row) * HH + k0 + c4];
            float4 tb = make_float4(tf32r(vb.x), tf32r(vb.y), tf32r(vb.z), tf32r(vb.w));
            *(float4*)&Bs[row * 36 + c4] = tb;
        }
        __syncthreads();

        #pragma unroll
        for (int ks = 0; ks < 4; ks++) {
            uint32_t a[4][4];
            #pragma unroll
            for (int mt = 0; mt < 4; mt++) {
                int r = wm * 64 + mt * 16 + g;
                a[mt][0] = fb(As[r * 36 + ks * 8 + tg]);
                a[mt][1] = fb(As[(r + 8) * 36 + ks * 8 + tg]);
                a[mt][2] = fb(As[r * 36 + ks * 8 + tg + 4]);
                a[mt][3] = fb(As[(r + 8) * 36 + ks * 8 + tg + 4]);
            }
            #pragma unroll
            for (int nt = 0; nt < 4; nt++) {
                int n = wn * 32 + nt * 8 + g;
                uint32_t b0 = fb(Bs[n * 36 + ks * 8 + tg]);
                uint32_t b1 = fb(Bs[n * 36 + ks * 8 + tg + 4]);
                #pragma unroll
                for (int mt = 0; mt < 4; mt++)
                    mma8(acc[mt][nt], a[mt][0], a[mt][1], a[mt][2], a[mt][3], b0, b1);
            }
        }
        __syncthreads();
    }

    #pragma unroll
    for (int mt = 0; mt < 4; mt++) {
        int r = m0 + wm * 64 + mt * 16 + g;
        int b_  = r >> 11, s_ = r & 2047;
        int b8_ = (r + 8) >> 11, s8_ = (r + 8) & 2047;
        #pragma unroll
        for (int nt = 0; nt < 4; nt++) {
            int c = n0 + wn * 32 + nt * 8 + 2 * tg;
            int nh = c >> 6, hd = c & 63;
            float bi0 = bias[c], bi1 = bias[c + 1];
            int h0 = (b_  << 4) + nh;
            int h8 = (b8_ << 4) + nh;
            if (vtrans) {
                int t0 = (h0 * HDD + hd) * SS + s_;
                int t8 = (h8 * HDD + hd) * SS + s8_;
                out[t0]      = acc[mt][nt][0] + bi0;
                out[t0 + SS] = acc[mt][nt][1] + bi1;
                out[t8]      = acc[mt][nt][2] + bi0;
                out[t8 + SS] = acc[mt][nt][3] + bi1;
            } else {
                int base0 = (h0 * SS + s_ ) * HDD + hd;
                int base8 = (h8 * SS + s8_) * HDD + hd;
                out[base0]     = acc[mt][nt][0] + bi0;
                out[base0 + 1] = acc[mt][nt][1] + bi1;
                out[base8]     = acc[mt][nt][2] + bi0;
                out[base8 + 1] = acc[mt][nt][3] + bi1;
            }
        }
    }
}

// ======================= Flash attention =======================
// CTA: 8 warps, 256 query rows (32/warp, mt=2 m-tiles). K-tile = 64 keys.
// Each B fragment (K and V^T) loaded once per warp feeds TWO mmas.
#define KSTR 68

__global__ __launch_bounds__(256, 1) void attn_kernel(const float* __restrict__ mask,
                                                      float* __restrict__ out)
{
    __shared__ float Ks[64 * KSTR];
    __shared__ float Vt[64 * KSTR];   // V^T tile: [hd][key]
    __shared__ float Ms[64];

    const int tid = threadIdx.x;
    const int lane = tid & 31, warp = tid >> 5;
    const int g = lane >> 2, tg = lane & 3;
    const int hbh = blockIdx.y;            // 0..63
    const int b = hbh >> 4, nh = hbh & 15;
    const int q0 = blockIdx.x * 256;
    const int r0 = warp * 32;              // 32 rows per warp

    const float* qb  = g_q + ((size_t)hbh * SS + q0) * HDD;
    const float* kb  = g_k + (size_t)hbh * SS * HDD;
    const float* vtb = g_v + (size_t)hbh * HDD * SS;

    // Q fragments (2 m-tiles) -> registers, pre-scaled, tf32-rounded
    uint32_t qa[2][8][4];
    #pragma unroll
    for (int mt = 0; mt < 2; mt++) {
        int rr = r0 + mt * 16;
        #pragma unroll
        for (int ks = 0; ks < 8; ks++) {
            qa[mt][ks][0] = fb(tf32r(qb[(rr + g)     * 64 + ks * 8 + tg]     * 0.125f));
            qa[mt][ks][1] = fb(tf32r(qb[(rr + 8 + g) * 64 + ks * 8 + tg]     * 0.125f));
            qa[mt][ks][2] = fb(tf32r(qb[(rr + g)     * 64 + ks * 8 + tg + 4] * 0.125f));
            qa[mt][ks][3] = fb(tf32r(qb[(rr + 8 + g) * 64 + ks * 8 + tg + 4] * 0.125f));
        }
    }

    float O[2][8][4];
    #pragma unroll
    for (int mt = 0; mt < 2; mt++)
        #pragma unroll
        for (int nt = 0; nt < 8; nt++)
            #pragma unroll
            for (int j = 0; j < 4; j++) O[mt][nt][j] = 0.f;
    float mrow[4] = {-1e30f, -1e30f, -1e30f, -1e30f};
    float lrow[4] = {0.f, 0.f, 0.f, 0.f};

    const int srcA = (lane & ~3) | (tg >> 1);
    const int srcB = srcA + 2;
    const bool odd = (tg & 1);

    for (int kt = 0; kt < 32; kt++) {
        __syncthreads();
        // Fill K tile [key][hd] and V^T tile [hd][key]
        #pragma unroll
        for (int i = 0; i < 4; i++) {
            int idx = tid + i * 256;       // 0..1023 float4s
            int row = idx >> 4;
            int c4 = (idx & 15) * 4;
            float4 vk = *(const float4*)&kb[(kt * 64 + row) * 64 + c4];
            *(float4*)&Ks[row * KSTR + c4] =
                make_float4(tf32r(vk.x), tf32r(vk.y), tf32r(vk.z), tf32r(vk.w));
            float4 vv = *(const float4*)&vtb[(size_t)row * SS + kt * 64 + c4];
            *(float4*)&Vt[row * KSTR + c4] =
                make_float4(tf32r(vv.x), tf32r(vv.y), tf32r(vv.z), tf32r(vv.w));
        }
        if (tid < 64) Ms[tid] = mask[b * SS + kt * 64 + tid];
        __syncthreads();

        // S = Q K^T  (two 16-row m-tiles per warp share each B fragment)
        float s[2][8][4];
        #pragma unroll
        for (int mt = 0; mt < 2; mt++)
            #pragma unroll
            for (int nt = 0; nt < 8; nt++)
                #pragma unroll
                for (int j = 0; j < 4; j++) s[mt][nt][j] = 0.f;

        #pragma unroll
        for (int ks = 0; ks < 8; ks++) {
            #pragma unroll
            for (int nt = 0; nt < 8; nt++) {
                uint32_t b0 = fb(Ks[(nt * 8 + g) * KSTR + ks * 8 + tg]);
                uint32_t b1 = fb(Ks[(nt * 8 + g) * KSTR + ks * 8 + tg + 4]);
                mma8(s[0][nt], qa[0][ks][0], qa[0][ks][1], qa[0][ks][2], qa[0][ks][3], b0, b1);
                mma8(s[1][nt], qa[1][ks][0], qa[1][ks][1], qa[1][ks][2], qa[1][ks][3], b0, b1);
            }
        }

        // mask + online softmax per m-tile
        #pragma unroll
        for (int mt = 0; mt < 2; mt++) {
            float mx0 = -1e30f, mx1 = -1e30f;
            #pragma unroll
            for (int nt = 0; nt < 8; nt++) {
                float mk0 = Ms[nt * 8 + 2 * tg], mk1 = Ms[nt * 8 + 2 * tg + 1];
                s[mt][nt][0] += mk0; s[mt][nt][1] += mk1;
                s[mt][nt][2] += mk0; s[mt][nt][3] += mk1;
                mx0 = fmaxf(mx0, fmaxf(s[mt][nt][0], s[mt][nt][1]));
                mx1 = fmaxf(mx1, fmaxf(s[mt][nt][2], s[mt][nt][3]));
            }
            mx0 = fmaxf(mx0, __shfl_xor_sync(0xffffffffu, mx0, 1));
            mx0 = fmaxf(mx0, __shfl_xor_sync(0xffffffffu, mx0, 2));
            mx1 = fmaxf(mx1, __shfl_xor_sync(0xffffffffu, mx1, 1));
            mx1 = fmaxf(mx1, __shfl_xor_sync(0xffffffffu, mx1, 2));

            float mn0 = fmaxf(mrow[mt * 2],     mx0);
            float mn1 = fmaxf(mrow[mt * 2 + 1], mx1);
            float al0 = __expf(mrow[mt * 2]     - mn0);
            float al1 = __expf(mrow[mt * 2 + 1] - mn1);
            mrow[mt * 2] = mn0; mrow[mt * 2 + 1] = mn1;

            float ls0 = 0.f, ls1 = 0.f;
            #pragma unroll
            for (int nt = 0; nt < 8; nt++) {
                float p0 = __expf(s[mt][nt][0] - mn0);
                float p1 = __expf(s[mt][nt][1] - mn0);
                float p2 = __expf(s[mt][nt][2] - mn1);
                float p3 = __expf(s[mt][nt][3] - mn1);
                ls0 += p0 + p1; ls1 += p2 + p3;
                s[mt][nt][0] = tf32r(p0); s[mt][nt][1] = tf32r(p1);
                s[mt][nt][2] = tf32r(p2); s[mt][nt][3] = tf32r(p3);
            }
            ls0 += __shfl_xor_sync(0xffffffffu, ls0, 1);
            ls0 += __shfl_xor_sync(0xffffffffu, ls0, 2);
            ls1 += __shfl_xor_sync(0xffffffffu, ls1, 1);
            ls1 += __shfl_xor_sync(0xffffffffu, ls1, 2);
            lrow[mt * 2]     = lrow[mt * 2]     * al0 + ls0;
            lrow[mt * 2 + 1] = lrow[mt * 2 + 1] * al1 + ls1;

            #pragma unroll
            for (int nt = 0; nt < 8; nt++) {
                O[mt][nt][0] *= al0; O[mt][nt][1] *= al0;
                O[mt][nt][2] *= al1; O[mt][nt][3] *= al1;
            }
        }

        // O += P V : shuffle-convert P per m-tile; each V fragment feeds 2 mmas
        #pragma unroll
        for (int ks = 0; ks < 8; ks++) {
            uint32_t a[2][4];
            #pragma unroll
            for (int mt = 0; mt < 2; mt++) {
                float x0 = __shfl_sync(0xffffffffu, s[mt][ks][0], srcA);
                float x1 = __shfl_sync(0xffffffffu, s[mt][ks][1], srcA);
                float y0 = __shfl_sync(0xffffffffu, s[mt][ks][0], srcB);
                float y1 = __shfl_sync(0xffffffffu, s[mt][ks][1], srcB);
                float z0 = __shfl_sync(0xffffffffu, s[mt][ks][2], srcA);
                float z1 = __shfl_sync(0xffffffffu, s[mt][ks][3], srcA);
                float w0 = __shfl_sync(0xffffffffu, s[mt][ks][2], srcB);
                float w1 = __shfl_sync(0xffffffffu, s[mt][ks][3], srcB);
                a[mt][0] = fb(odd ? x1 : x0);
                a[mt][2] = fb(odd ? y1 : y0);
                a[mt][1] = fb(odd ? z1 : z0);
                a[mt][3] = fb(odd ? w1 : w0);
            }
            #pragma unroll
            for (int nt = 0; nt < 8; nt++) {
                uint32_t b0 = fb(Vt[(nt * 8 + g) * KSTR + ks * 8 + tg]);
                uint32_t b1 = fb(Vt[(nt * 8 + g) * KSTR + ks * 8 + tg + 4]);
                mma8(O[0][nt], a[0][0], a[0][1], a[0][2], a[0][3], b0, b1);
                mma8(O[1][nt], a[1][0], a[1][1], a[1][2], a[1][3], b0, b1);
            }
        }
    }

    // Normalize + write [B,S,H]
    #pragma unroll
    for (int mt = 0; mt < 2; mt++) {
        float i0 = 1.f / lrow[mt * 2], i1 = 1.f / lrow[mt * 2 + 1];
        int rg  = q0 + r0 + mt * 16 + g;
        int rg8 = rg + 8;
        #pragma unroll
        for (int nt = 0; nt < 8; nt++) {
            int hd = nt * 8 + 2 * tg;
            int o0 = (b * SS + rg ) * HH + nh * 64 + hd;
            int o8 = (b * SS + rg8) * HH + nh * 64 + hd;
            out[o0]     = O[mt][nt][0] * i0;
            out[o0 + 1] = O[mt][nt][1] * i0;
            out[o8]     = O[mt][nt][2] * i1;
            out[o8 + 1] = O[mt][nt][3] * i1;
        }
    }
}

extern "C" void kernel_launch(void* const* d_in, const int* in_sizes, int n_in,
                              void* d_out, int out_size)
{
    const float* X    = (const float*)d_in[0];
    const float* mask = (const float*)d_in[1];
    const float* Wq   = (const float*)d_in[2];
    const float* bq   = (const float*)d_in[3];
    const float* Wk   = (const float*)d_in[4];
    const float* bk   = (const float*)d_in[5];
    const float* Wv   = (const float*)d_in[6];
    const float* bv   = (const float*)d_in[7];
    float* out = (float*)d_out;

    dim3 gg(8192 / 128, HH / 128, 3);
    qkv_gemm_kernel<<<gg, 256>>>(X, Wq, bq, Wk, bk, Wv, bv);

    dim3 ga(SS / 256, BH);
    attn_kernel<<<ga, 256>>>(mask, out);
}

// round 4
// speedup vs baseline: 1.1013x; 1.1013x over previous
#include <cuda_runtime.h>
#include <cstdint>

#define BB 4
#define SS 2048
#define HH 1024
#define NHH 16
#define HDD 64
#define BH (BB*NHH)   // 64 heads total

// Scratch (pre-rounded to tf32 by the GEMM epilogue):
// Q (pre-scaled by 0.125), K head-major [B*NH][S][HD]; V transposed [B*NH][HD][S]
__device__ float g_q[BB*SS*HH];
__device__ float g_k[BB*SS*HH];
__device__ float g_v[BB*SS*HH];

__device__ __forceinline__ float tf32r(float x) {
    uint32_t r;
    asm("cvt.rna.tf32.f32 %0, %1;" : "=r"(r) : "f"(x));
    return __uint_as_float(r);
}
__device__ __forceinline__ uint32_t fb(float x) { return __float_as_uint(x); }

__device__ __forceinline__ void mma8(float c[4],
                                     uint32_t a0, uint32_t a1, uint32_t a2, uint32_t a3,
                                     uint32_t b0, uint32_t b1) {
    asm volatile(
        "mma.sync.aligned.m16n8k8.row.col.f32.tf32.tf32.f32 "
        "{%0,%1,%2,%3},{%4,%5,%6,%7},{%8,%9},{%0,%1,%2,%3};\n"
        : "+f"(c[0]), "+f"(c[1]), "+f"(c[2]), "+f"(c[3])
        : "r"(a0), "r"(a1), "r"(a2), "r"(a3), "r"(b0), "r"(b1));
}

__device__ __forceinline__ void cpasync16(uint32_t dst_smem, const void* src) {
    asm volatile("cp.async.cg.shared.global [%0], [%1], 16;\n"
                 :: "r"(dst_smem), "l"(src));
}
__device__ __forceinline__ void cpcommit() {
    asm volatile("cp.async.commit_group;\n");
}
__device__ __forceinline__ void cpwait0() {
    asm volatile("cp.async.wait_group 0;\n");
}

// ======================= QKV projection GEMM =======================
// Epilogue now emits tf32-rounded values (Q additionally pre-scaled by 0.125).
__global__ __launch_bounds__(256) void qkv_gemm_kernel(
    const float* __restrict__ X,
    const float* __restrict__ Wq, const float* __restrict__ bq,
    const float* __restrict__ Wk, const float* __restrict__ bk,
    const float* __restrict__ Wv, const float* __restrict__ bv)
{
    __shared__ float As[128 * 36];
    __shared__ float Bs[128 * 36];

    const float* W; const float* bias; float* out;
    if (blockIdx.z == 0)      { W = Wq; bias = bq; out = g_q; }
    else if (blockIdx.z == 1) { W = Wk; bias = bk; out = g_k; }
    else                      { W = Wv; bias = bv; out = g_v; }
    const bool vtrans = (blockIdx.z == 2);
    const float oscale = (blockIdx.z == 0) ? 0.125f : 1.0f;

    const int m0 = blockIdx.x * 128;
    const int n0 = blockIdx.y * 128;
    const int tid = threadIdx.x;
    const int lane = tid & 31, warp = tid >> 5;
    const int wm = warp >> 2, wn = warp & 3;
    const int g = lane >> 2, tg = lane & 3;

    float acc[4][4][4];
    #pragma unroll
    for (int mt = 0; mt < 4; mt++)
        #pragma unroll
        for (int nt = 0; nt < 4; nt++)
            #pragma unroll
            for (int j = 0; j < 4; j++) acc[mt][nt][j] = 0.f;

    for (int k0 = 0; k0 < HH; k0 += 32) {
        #pragma unroll
        for (int i = 0; i < 4; i++) {
            int idx = tid + i * 256;
            int row = idx >> 3;
            int c4  = (idx & 7) * 4;
            float4 va = *(const float4*)&X[(size_t)(m0 + row) * HH + k0 + c4];
            *(float4*)&As[row * 36 + c4] =
                make_float4(tf32r(va.x), tf32r(va.y), tf32r(va.z), tf32r(va.w));
            float4 vb = *(const float4*)&W[(size_t)(n0 + row) * HH + k0 + c4];
            *(float4*)&Bs[row * 36 + c4] =
                make_float4(tf32r(vb.x), tf32r(vb.y), tf32r(vb.z), tf32r(vb.w));
        }
        __syncthreads();

        #pragma unroll
        for (int ks = 0; ks < 4; ks++) {
            uint32_t a[4][4];
            #pragma unroll
            for (int mt = 0; mt < 4; mt++) {
                int r = wm * 64 + mt * 16 + g;
                a[mt][0] = fb(As[r * 36 + ks * 8 + tg]);
                a[mt][1] = fb(As[(r + 8) * 36 + ks * 8 + tg]);
                a[mt][2] = fb(As[r * 36 + ks * 8 + tg + 4]);
                a[mt][3] = fb(As[(r + 8) * 36 + ks * 8 + tg + 4]);
            }
            #pragma unroll
            for (int nt = 0; nt < 4; nt++) {
                int n = wn * 32 + nt * 8 + g;
                uint32_t b0 = fb(Bs[n * 36 + ks * 8 + tg]);
                uint32_t b1 = fb(Bs[n * 36 + ks * 8 + tg + 4]);
                #pragma unroll
                for (int mt = 0; mt < 4; mt++)
                    mma8(acc[mt][nt], a[mt][0], a[mt][1], a[mt][2], a[mt][3], b0, b1);
            }
        }
        __syncthreads();
    }

    #pragma unroll
    for (int mt = 0; mt < 4; mt++) {
        int r = m0 + wm * 64 + mt * 16 + g;
        int b_  = r >> 11, s_ = r & 2047;
        int b8_ = (r + 8) >> 11, s8_ = (r + 8) & 2047;
        #pragma unroll
        for (int nt = 0; nt < 4; nt++) {
            int c = n0 + wn * 32 + nt * 8 + 2 * tg;
            int nh = c >> 6, hd = c & 63;
            float bi0 = bias[c], bi1 = bias[c + 1];
            int h0 = (b_  << 4) + nh;
            int h8 = (b8_ << 4) + nh;
            float v0 = tf32r((acc[mt][nt][0] + bi0) * oscale);
            float v1 = tf32r((acc[mt][nt][1] + bi1) * oscale);
            float v2 = tf32r((acc[mt][nt][2] + bi0) * oscale);
            float v3 = tf32r((acc[mt][nt][3] + bi1) * oscale);
            if (vtrans) {
                int t0 = (h0 * HDD + hd) * SS + s_;
                int t8 = (h8 * HDD + hd) * SS + s8_;
                out[t0]      = v0;
                out[t0 + SS] = v1;
                out[t8]      = v2;
                out[t8 + SS] = v3;
            } else {
                int base0 = (h0 * SS + s_ ) * HDD + hd;
                int base8 = (h8 * SS + s8_) * HDD + hd;
                out[base0]     = v0;
                out[base0 + 1] = v1;
                out[base8]     = v2;
                out[base8 + 1] = v3;
            }
        }
    }
}

// ======================= Flash attention =======================
// CTA: 8 warps, 128 query rows (16/warp). Double-buffered cp.async K/V tiles,
// tf32 pre-rounded in scratch (no conversion in this kernel). Mask preloaded.
#define KSTR 68
#define TILE_F (64 * KSTR)                 // floats per tile stage
#define ATTN_SMEM ((4 * TILE_F + SS) * (int)sizeof(float))

__global__ __launch_bounds__(256, 2) void attn_kernel(const float* __restrict__ mask,
                                                      float* __restrict__ out)
{
    extern __shared__ float sm[];
    // [0 .. 2*TILE_F)   : Ks stage 0 / stage 1
    // [2T .. 4*TILE_F)  : Vt stage 0 / stage 1
    float* Msk = sm + 4 * TILE_F;          // 2048 floats

    const int tid = threadIdx.x;
    const int lane = tid & 31, warp = tid >> 5;
    const int g = lane >> 2, tg = lane & 3;
    const int hbh = blockIdx.y;            // 0..63
    const int b = hbh >> 4, nh = hbh & 15;
    const int q0 = blockIdx.x * 128;
    const int r0 = warp * 16;

    const float* qb  = g_q + ((size_t)hbh * SS + q0) * HDD;
    const float* kb  = g_k + (size_t)hbh * SS * HDD;
    const float* vtb = g_v + (size_t)hbh * HDD * SS;

    // Preload full mask row for this batch (zeros in practice, but general)
    {
        const float* mrow = mask + b * SS;
        #pragma unroll
        for (int i = 0; i < 2; i++) {
            int idx = tid + i * 256;       // 512 float4s
            *(float4*)&Msk[idx * 4] = *(const float4*)&mrow[idx * 4];
        }
    }

    // Q fragments -> registers (already tf32-rounded & scaled in scratch)
    uint32_t qa[8][4];
    #pragma unroll
    for (int ks = 0; ks < 8; ks++) {
        qa[ks][0] = fb(qb[(r0 + g)     * 64 + ks * 8 + tg]);
        qa[ks][1] = fb(qb[(r0 + 8 + g) * 64 + ks * 8 + tg]);
        qa[ks][2] = fb(qb[(r0 + g)     * 64 + ks * 8 + tg + 4]);
        qa[ks][3] = fb(qb[(r0 + 8 + g) * 64 + ks * 8 + tg + 4]);
    }

    // Per-thread fill slice: 4 chunks of 16B into Ks, 4 into Vt per stage.
    // chunk c (0..1023): row = c>>4, col4 = (c&15)*4
    const uint32_t smem_base = (uint32_t)__cvta_generic_to_shared(sm);

    float O[8][4];
    #pragma unroll
    for (int nt = 0; nt < 8; nt++)
        #pragma unroll
        for (int j = 0; j < 4; j++) O[nt][j] = 0.f;
    float m0s = -1e30f, m1s = -1e30f, l0 = 0.f, l1 = 0.f;

    const int srcA = (lane & ~3) | (tg >> 1);
    const int srcB = srcA + 2;
    const bool odd = (tg & 1);

    // Issue fill for tile 0, stage 0
    {
        #pragma unroll
        for (int i = 0; i < 4; i++) {
            int c = tid + i * 256;
            int row = c >> 4, c4 = (c & 15) * 4;
            cpasync16(smem_base + (row * KSTR + c4) * 4, &kb[row * 64 + c4]);
            cpasync16(smem_base + (2 * TILE_F + row * KSTR + c4) * 4,
                      &vtb[(size_t)row * SS + c4]);
        }
        cpcommit();
    }

    for (int kt = 0; kt < 32; kt++) {
        const int cur = kt & 1;
        float* Ks = sm + cur * TILE_F;
        float* Vt = sm + 2 * TILE_F + cur * TILE_F;

        cpwait0();
        __syncthreads();

        // Prefetch next tile into the other stage
        if (kt + 1 < 32) {
            const int nxt = (kt + 1) & 1;
            const int koff = (kt + 1) * 64;
            #pragma unroll
            for (int i = 0; i < 4; i++) {
                int c = tid + i * 256;
                int row = c >> 4, c4 = (c & 15) * 4;
                cpasync16(smem_base + (nxt * TILE_F + row * KSTR + c4) * 4,
                          &kb[(koff + row) * 64 + c4]);
                cpasync16(smem_base + ((2 + nxt) * TILE_F + row * KSTR + c4) * 4,
                          &vtb[(size_t)row * SS + koff + c4]);
            }
            cpcommit();
        }

        // S = Q K^T
        float s[8][4];
        #pragma unroll
        for (int nt = 0; nt < 8; nt++)
            #pragma unroll
            for (int j = 0; j < 4; j++) s[nt][j] = 0.f;

        #pragma unroll
        for (int ks = 0; ks < 8; ks++) {
            #pragma unroll
            for (int nt = 0; nt < 8; nt++) {
                uint32_t b0 = fb(Ks[(nt * 8 + g) * KSTR + ks * 8 + tg]);
                uint32_t b1 = fb(Ks[(nt * 8 + g) * KSTR + ks * 8 + tg + 4]);
                mma8(s[nt], qa[ks][0], qa[ks][1], qa[ks][2], qa[ks][3], b0, b1);
            }
        }

        // mask + row max
        const float* Mt = Msk + kt * 64;
        float mx0 = -1e30f, mx1 = -1e30f;
        #pragma unroll
        for (int nt = 0; nt < 8; nt++) {
            float mk0 = Mt[nt * 8 + 2 * tg], mk1 = Mt[nt * 8 + 2 * tg + 1];
            s[nt][0] += mk0; s[nt][1] += mk1; s[nt][2] += mk0; s[nt][3] += mk1;
            mx0 = fmaxf(mx0, fmaxf(s[nt][0], s[nt][1]));
            mx1 = fmaxf(mx1, fmaxf(s[nt][2], s[nt][3]));
        }
        mx0 = fmaxf(mx0, __shfl_xor_sync(0xffffffffu, mx0, 1));
        mx0 = fmaxf(mx0, __shfl_xor_sync(0xffffffffu, mx0, 2));
        mx1 = fmaxf(mx1, __shfl_xor_sync(0xffffffffu, mx1, 1));
        mx1 = fmaxf(mx1, __shfl_xor_sync(0xffffffffu, mx1, 2));

        float mn0 = fmaxf(m0s, mx0), mn1 = fmaxf(m1s, mx1);
        float al0 = __expf(m0s - mn0), al1 = __expf(m1s - mn1);
        m0s = mn0; m1s = mn1;

        float ls0 = 0.f, ls1 = 0.f;
        #pragma unroll
        for (int nt = 0; nt < 8; nt++) {
            float p0 = __expf(s[nt][0] - mn0);
            float p1 = __expf(s[nt][1] - mn0);
            float p2 = __expf(s[nt][2] - mn1);
            float p3 = __expf(s[nt][3] - mn1);
            ls0 += p0 + p1; ls1 += p2 + p3;
            s[nt][0] = tf32r(p0); s[nt][1] = tf32r(p1);
            s[nt][2] = tf32r(p2); s[nt][3] = tf32r(p3);
        }
        ls0 += __shfl_xor_sync(0xffffffffu, ls0, 1);
        ls0 += __shfl_xor_sync(0xffffffffu, ls0, 2);
        ls1 += __shfl_xor_sync(0xffffffffu, ls1, 1);
        ls1 += __shfl_xor_sync(0xffffffffu, ls1, 2);
        l0 = l0 * al0 + ls0;
        l1 = l1 * al1 + ls1;

        #pragma unroll
        for (int nt = 0; nt < 8; nt++) {
            O[nt][0] *= al0; O[nt][1] *= al0; O[nt][2] *= al1; O[nt][3] *= al1;
        }

        // O += P V : shuffle-convert P accumulator-layout -> A-operand layout
        #pragma unroll
        for (int ks = 0; ks < 8; ks++) {
            float x0 = __shfl_sync(0xffffffffu, s[ks][0], srcA);
            float x1 = __shfl_sync(0xffffffffu, s[ks][1], srcA);
            float y0 = __shfl_sync(0xffffffffu, s[ks][0], srcB);
            float y1 = __shfl_sync(0xffffffffu, s[ks][1], srcB);
            float z0 = __shfl_sync(0xffffffffu, s[ks][2], srcA);
            float z1 = __shfl_sync(0xffffffffu, s[ks][3], srcA);
            float w0 = __shfl_sync(0xffffffffu, s[ks][2], srcB);
            float w1 = __shfl_sync(0xffffffffu, s[ks][3], srcB);
            uint32_t a0 = fb(odd ? x1 : x0);
            uint32_t a2 = fb(odd ? y1 : y0);
            uint32_t a1 = fb(odd ? z1 : z0);
            uint32_t a3 = fb(odd ? w1 : w0);
            #pragma unroll
            for (int nt = 0; nt < 8; nt++) {
                uint32_t b0 = fb(Vt[(nt * 8 + g) * KSTR + ks * 8 + tg]);
                uint32_t b1 = fb(Vt[(nt * 8 + g) * KSTR + ks * 8 + tg + 4]);
                mma8(O[nt], a0, a1, a2, a3, b0, b1);
            }
        }
    }

    // Normalize + write [B,S,H]
    float i0 = 1.f / l0, i1 = 1.f / l1;
    int rg  = q0 + r0 + g;
    int rg8 = rg + 8;
    #pragma unroll
    for (int nt = 0; nt < 8; nt++) {
        int hd = nt * 8 + 2 * tg;
        int o0 = (b * SS + rg ) * HH + nh * 64 + hd;
        int o8 = (b * SS + rg8) * HH + nh * 64 + hd;
        out[o0]     = O[nt][0] * i0;
        out[o0 + 1] = O[nt][1] * i0;
        out[o8]     = O[nt][2] * i1;
        out[o8 + 1] = O[nt][3] * i1;
    }
}

extern "C" void kernel_launch(void* const* d_in, const int* in_sizes, int n_in,
                              void* d_out, int out_size)
{
    const float* X    = (const float*)d_in[0];
    const float* mask = (const float*)d_in[1];
    const float* Wq   = (const float*)d_in[2];
    const float* bq   = (const float*)d_in[3];
    const float* Wk   = (const float*)d_in[4];
    const float* bk   = (const float*)d_in[5];
    const float* Wv   = (const float*)d_in[6];
    const float* bv   = (const float*)d_in[7];
    float* out = (float*)d_out;

    cudaFuncSetAttribute(attn_kernel, cudaFuncAttributeMaxDynamicSharedMemorySize, ATTN_SMEM);

    dim3 gg(8192 / 128, HH / 128, 3);
    qkv_gemm_kernel<<<gg, 256>>>(X, Wq, bq, Wk, bk, Wv, bv);

    dim3 ga(SS / 128, BH);
    attn_kernel<<<ga, 256, ATTN_SMEM>>>(mask, out);
}

// round 5
// speedup vs baseline: 1.1024x; 1.0010x over previous
#include <cuda_runtime.h>
#include <cstdint>

#define BB 4
#define SS 2048
#define HH 1024
#define NHH 16
#define HDD 64
#define BH (BB*NHH)   // 64 heads total

// Scratch (pre-rounded to tf32 by the GEMM epilogue):
// Q (pre-scaled by 0.125), K head-major [B*NH][S][HD]; V transposed [B*NH][HD][S]
__device__ float g_q[BB*SS*HH];
__device__ float g_k[BB*SS*HH];
__device__ float g_v[BB*SS*HH];

__device__ __forceinline__ float tf32r(float x) {
    uint32_t r;
    asm("cvt.rna.tf32.f32 %0, %1;" : "=r"(r) : "f"(x));
    return __uint_as_float(r);
}
__device__ __forceinline__ uint32_t fb(float x) { return __float_as_uint(x); }

__device__ __forceinline__ void mma8(float c[4],
                                     uint32_t a0, uint32_t a1, uint32_t a2, uint32_t a3,
                                     uint32_t b0, uint32_t b1) {
    asm volatile(
        "mma.sync.aligned.m16n8k8.row.col.f32.tf32.tf32.f32 "
        "{%0,%1,%2,%3},{%4,%5,%6,%7},{%8,%9},{%0,%1,%2,%3};\n"
        : "+f"(c[0]), "+f"(c[1]), "+f"(c[2]), "+f"(c[3])
        : "r"(a0), "r"(a1), "r"(a2), "r"(a3), "r"(b0), "r"(b1));
}

__device__ __forceinline__ void cpasync16(uint32_t dst_smem, const void* src) {
    asm volatile("cp.async.cg.shared.global [%0], [%1], 16;\n"
                 :: "r"(dst_smem), "l"(src));
}
__device__ __forceinline__ void cpcommit() {
    asm volatile("cp.async.commit_group;\n");
}
__device__ __forceinline__ void cpwait0() {
    asm volatile("cp.async.wait_group 0;\n");
}

// ======================= QKV projection GEMM =======================
// Epilogue now emits tf32-rounded values (Q additionally pre-scaled by 0.125).
__global__ __launch_bounds__(256) void qkv_gemm_kernel(
    const float* __restrict__ X,
    const float* __restrict__ Wq, const float* __restrict__ bq,
    const float* __restrict__ Wk, const float* __restrict__ bk,
    const float* __restrict__ Wv, const float* __restrict__ bv)
{
    __shared__ float As[128 * 36];
    __shared__ float Bs[128 * 36];

    const float* W; const float* bias; float* out;
    if (blockIdx.z == 0)      { W = Wq; bias = bq; out = g_q; }
    else if (blockIdx.z == 1) { W = Wk; bias = bk; out = g_k; }
    else                      { W = Wv; bias = bv; out = g_v; }
    const bool vtrans = (blockIdx.z == 2);
    const float oscale = (blockIdx.z == 0) ? 0.125f : 1.0f;

    const int m0 = blockIdx.x * 128;
    const int n0 = blockIdx.y * 128;
    const int tid = threadIdx.x;
    const int lane = tid & 31, warp = tid >> 5;
    const int wm = warp >> 2, wn = warp & 3;
    const int g = lane >> 2, tg = lane & 3;

    float acc[4][4][4];
    #pragma unroll
    for (int mt = 0; mt < 4; mt++)
        #pragma unroll
        for (int nt = 0; nt < 4; nt++)
            #pragma unroll
            for (int j = 0; j < 4; j++) acc[mt][nt][j] = 0.f;

    for (int k0 = 0; k0 < HH; k0 += 32) {
        #pragma unroll
        for (int i = 0; i < 4; i++) {
            int idx = tid + i * 256;
            int row = idx >> 3;
            int c4  = (idx & 7) * 4;
            float4 va = *(const float4*)&X[(size_t)(m0 + row) * HH + k0 + c4];
            *(float4*)&As[row * 36 + c4] =
                make_float4(tf32r(va.x), tf32r(va.y), tf32r(va.z), tf32r(va.w));
            float4 vb = *(const float4*)&W[(size_t)(n0 + row) * HH + k0 + c4];
            *(float4*)&Bs[row * 36 + c4] =
                make_float4(tf32r(vb.x), tf32r(vb.y), tf32r(vb.z), tf32r(vb.w));
        }
        __syncthreads();

        #pragma unroll
        for (int ks = 0; ks < 4; ks++) {
            uint32_t a[4][4];
            #pragma unroll
            for (int mt = 0; mt < 4; mt++) {
                int r = wm * 64 + mt * 16 + g;
                a[mt][0] = fb(As[r * 36 + ks * 8 + tg]);
                a[mt][1] = fb(As[(r + 8) * 36 + ks * 8 + tg]);
                a[mt][2] = fb(As[r * 36 + ks * 8 + tg + 4]);
                a[mt][3] = fb(As[(r + 8) * 36 + ks * 8 + tg + 4]);
            }
            #pragma unroll
            for (int nt = 0; nt < 4; nt++) {
                int n = wn * 32 + nt * 8 + g;
                uint32_t b0 = fb(Bs[n * 36 + ks * 8 + tg]);
                uint32_t b1 = fb(Bs[n * 36 + ks * 8 + tg + 4]);
                #pragma unroll
                for (int mt = 0; mt < 4; mt++)
                    mma8(acc[mt][nt], a[mt][0], a[mt][1], a[mt][2], a[mt][3], b0, b1);
            }
        }
        __syncthreads();
    }

    #pragma unroll
    for (int mt = 0; mt < 4; mt++) {
        int r = m0 + wm * 64 + mt * 16 + g;
        int b_  = r >> 11, s_ = r & 2047;
        int b8_ = (r + 8) >> 11, s8_ = (r + 8) & 2047;
        #pragma unroll
        for (int nt = 0; nt < 4; nt++) {
            int c = n0 + wn * 32 + nt * 8 + 2 * tg;
            int nh = c >> 6, hd = c & 63;
            float bi0 = bias[c], bi1 = bias[c + 1];
            int h0 = (b_  << 4) + nh;
            int h8 = (b8_ << 4) + nh;
            float v0 = tf32r((acc[mt][nt][0] + bi0) * oscale);
            float v1 = tf32r((acc[mt][nt][1] + bi1) * oscale);
            float v2 = tf32r((acc[mt][nt][2] + bi0) * oscale);
            float v3 = tf32r((acc[mt][nt][3] + bi1) * oscale);
            if (vtrans) {
                int t0 = (h0 * HDD + hd) * SS + s_;
                int t8 = (h8 * HDD + hd) * SS + s8_;
                out[t0]      = v0;
                out[t0 + SS] = v1;
                out[t8]      = v2;
                out[t8 + SS] = v3;
            } else {
                int base0 = (h0 * SS + s_ ) * HDD + hd;
                int base8 = (h8 * SS + s8_) * HDD + hd;
                out[base0]     = v0;
                out[base0 + 1] = v1;
                out[base8]     = v2;
                out[base8 + 1] = v3;
            }
        }
    }
}

// ======================= Flash attention =======================
// CTA: 8 warps, 128 query rows (16/warp). Double-buffered cp.async K/V tiles,
// tf32 pre-rounded in scratch (no conversion in this kernel). Mask preloaded.
#define KSTR 68
#define TILE_F (64 * KSTR)                 // floats per tile stage
#define ATTN_SMEM ((4 * TILE_F + SS) * (int)sizeof(float))

__global__ __launch_bounds__(256, 2) void attn_kernel(const float* __restrict__ mask,
                                                      float* __restrict__ out)
{
    extern __shared__ float sm[];
    // [0 .. 2*TILE_F)   : Ks stage 0 / stage 1
    // [2T .. 4*TILE_F)  : Vt stage 0 / stage 1
    float* Msk = sm + 4 * TILE_F;          // 2048 floats

    const int tid = threadIdx.x;
    const int lane = tid & 31, warp = tid >> 5;
    const int g = lane >> 2, tg = lane & 3;
    const int hbh = blockIdx.y;            // 0..63
    const int b = hbh >> 4, nh = hbh & 15;
    const int q0 = blockIdx.x * 128;
    const int r0 = warp * 16;

    const float* qb  = g_q + ((size_t)hbh * SS + q0) * HDD;
    const float* kb  = g_k + (size_t)hbh * SS * HDD;
    const float* vtb = g_v + (size_t)hbh * HDD * SS;

    // Preload full mask row for this batch (zeros in practice, but general)
    {
        const float* mrow = mask + b * SS;
        #pragma unroll
        for (int i = 0; i < 2; i++) {
            int idx = tid + i * 256;       // 512 float4s
            *(float4*)&Msk[idx * 4] = *(const float4*)&mrow[idx * 4];
        }
    }

    // Q fragments -> registers (already tf32-rounded & scaled in scratch)
    uint32_t qa[8][4];
    #pragma unroll
    for (int ks = 0; ks < 8; ks++) {
        qa[ks][0] = fb(qb[(r0 + g)     * 64 + ks * 8 + tg]);
        qa[ks][1] = fb(qb[(r0 + 8 + g) * 64 + ks * 8 + tg]);
        qa[ks][2] = fb(qb[(r0 + g)     * 64 + ks * 8 + tg + 4]);
        qa[ks][3] = fb(qb[(r0 + 8 + g) * 64 + ks * 8 + tg + 4]);
    }

    // Per-thread fill slice: 4 chunks of 16B into Ks, 4 into Vt per stage.
    // chunk c (0..1023): row = c>>4, col4 = (c&15)*4
    const uint32_t smem_base = (uint32_t)__cvta_generic_to_shared(sm);

    float O[8][4];
    #pragma unroll
    for (int nt = 0; nt < 8; nt++)
        #pragma unroll
        for (int j = 0; j < 4; j++) O[nt][j] = 0.f;
    float m0s = -1e30f, m1s = -1e30f, l0 = 0.f, l1 = 0.f;

    const int srcA = (lane & ~3) | (tg >> 1);
    const int srcB = srcA + 2;
    const bool odd = (tg & 1);

    // Issue fill for tile 0, stage 0
    {
        #pragma unroll
        for (int i = 0; i < 4; i++) {
            int c = tid + i * 256;
            int row = c >> 4, c4 = (c & 15) * 4;
            cpasync16(smem_base + (row * KSTR + c4) * 4, &kb[row * 64 + c4]);
            cpasync16(smem_base + (2 * TILE_F + row * KSTR + c4) * 4,
                      &vtb[(size_t)row * SS + c4]);
        }
        cpcommit();
    }

    for (int kt = 0; kt < 32; kt++) {
        const int cur = kt & 1;
        float* Ks = sm + cur * TILE_F;
        float* Vt = sm + 2 * TILE_F + cur * TILE_F;

        cpwait0();
        __syncthreads();

        // Prefetch next tile into the other stage
        if (kt + 1 < 32) {
            const int nxt = (kt + 1) & 1;
            const int koff = (kt + 1) * 64;
            #pragma unroll
            for (int i = 0; i < 4; i++) {
                int c = tid + i * 256;
                int row = c >> 4, c4 = (c & 15) * 4;
                cpasync16(smem_base + (nxt * TILE_F + row * KSTR + c4) * 4,
                          &kb[(koff + row) * 64 + c4]);
                cpasync16(smem_base + ((2 + nxt) * TILE_F + row * KSTR + c4) * 4,
                          &vtb[(size_t)row * SS + koff + c4]);
            }
            cpcommit();
        }

        // S = Q K^T
        float s[8][4];
        #pragma unroll
        for (int nt = 0; nt < 8; nt++)
            #pragma unroll
            for (int j = 0; j < 4; j++) s[nt][j] = 0.f;

        #pragma unroll
        for (int ks = 0; ks < 8; ks++) {
            #pragma unroll
            for (int nt = 0; nt < 8; nt++) {
                uint32_t b0 = fb(Ks[(nt * 8 + g) * KSTR + ks * 8 + tg]);
                uint32_t b1 = fb(Ks[(nt * 8 + g) * KSTR + ks * 8 + tg + 4]);
                mma8(s[nt], qa[ks][0], qa[ks][1], qa[ks][2], qa[ks][3], b0, b1);
            }
        }

        // mask + row max
        const float* Mt = Msk + kt * 64;
        float mx0 = -1e30f, mx1 = -1e30f;
        #pragma unroll
        for (int nt = 0; nt < 8; nt++) {
            float mk0 = Mt[nt * 8 + 2 * tg], mk1 = Mt[nt * 8 + 2 * tg + 1];
            s[nt][0] += mk0; s[nt][1] += mk1; s[nt][2] += mk0; s[nt][3] += mk1;
            mx0 = fmaxf(mx0, fmaxf(s[nt][0], s[nt][1]));
            mx1 = fmaxf(mx1, fmaxf(s[nt][2], s[nt][3]));
        }
        mx0 = fmaxf(mx0, __shfl_xor_sync(0xffffffffu, mx0, 1));
        mx0 = fmaxf(mx0, __shfl_xor_sync(0xffffffffu, mx0, 2));
        mx1 = fmaxf(mx1, __shfl_xor_sync(0xffffffffu, mx1, 1));
        mx1 = fmaxf(mx1, __shfl_xor_sync(0xffffffffu, mx1, 2));

        float mn0 = fmaxf(m0s, mx0), mn1 = fmaxf(m1s, mx1);
        float al0 = __expf(m0s - mn0), al1 = __expf(m1s - mn1);
        m0s = mn0; m1s = mn1;

        float ls0 = 0.f, ls1 = 0.f;
        #pragma unroll
        for (int nt = 0; nt < 8; nt++) {
            float p0 = __expf(s[nt][0] - mn0);
            float p1 = __expf(s[nt][1] - mn0);
            float p2 = __expf(s[nt][2] - mn1);
            float p3 = __expf(s[nt][3] - mn1);
            ls0 += p0 + p1; ls1 += p2 + p3;
            s[nt][0] = tf32r(p0); s[nt][1] = tf32r(p1);
            s[nt][2] = tf32r(p2); s[nt][3] = tf32r(p3);
        }
        ls0 += __shfl_xor_sync(0xffffffffu, ls0, 1);
        ls0 += __shfl_xor_sync(0xffffffffu, ls0, 2);
        ls1 += __shfl_xor_sync(0xffffffffu, ls1, 1);
        ls1 += __shfl_xor_sync(0xffffffffu, ls1, 2);
        l0 = l0 * al0 + ls0;
        l1 = l1 * al1 + ls1;

        #pragma unroll
        for (int nt = 0; nt < 8; nt++) {
            O[nt][0] *= al0; O[nt][1] *= al0; O[nt][2] *= al1; O[nt][3] *= al1;
        }

        // O += P V : shuffle-convert P accumulator-layout -> A-operand layout
        #pragma unroll
        for (int ks = 0; ks < 8; ks++) {
            float x0 = __shfl_sync(0xffffffffu, s[ks][0], srcA);
            float x1 = __shfl_sync(0xffffffffu, s[ks][1], srcA);
            float y0 = __shfl_sync(0xffffffffu, s[ks][0], srcB);
            float y1 = __shfl_sync(0xffffffffu, s[ks][1], srcB);
            float z0 = __shfl_sync(0xffffffffu, s[ks][2], srcA);
            float z1 = __shfl_sync(0xffffffffu, s[ks][3], srcA);
            float w0 = __shfl_sync(0xffffffffu, s[ks][2], srcB);
            float w1 = __shfl_sync(0xffffffffu, s[ks][3], srcB);
            uint32_t a0 = fb(odd ? x1 : x0);
            uint32_t a2 = fb(odd ? y1 : y0);
            uint32_t a1 = fb(odd ? z1 : z0);
            uint32_t a3 = fb(odd ? w1 : w0);
            #pragma unroll
            for (int nt = 0; nt < 8; nt++) {
                uint32_t b0 = fb(Vt[(nt * 8 + g) * KSTR + ks * 8 + tg]);
                uint32_t b1 = fb(Vt[(nt * 8 + g) * KSTR + ks * 8 + tg + 4]);
                mma8(O[nt], a0, a1, a2, a3, b0, b1);
            }
        }
    }

    // Normalize + write [B,S,H]
    float i0 = 1.f / l0, i1 = 1.f / l1;
    int rg  = q0 + r0 + g;
    int rg8 = rg + 8;
    #pragma unroll
    for (int nt = 0; nt < 8; nt++) {
        int hd = nt * 8 + 2 * tg;
        int o0 = (b * SS + rg ) * HH + nh * 64 + hd;
        int o8 = (b * SS + rg8) * HH + nh * 64 + hd;
        out[o0]     = O[nt][0] * i0;
        out[o0 + 1] = O[nt][1] * i0;
        out[o8]     = O[nt][2] * i1;
        out[o8 + 1] = O[nt][3] * i1;
    }
}

extern "C" void kernel_launch(void* const* d_in, const int* in_sizes, int n_in,
                              void* d_out, int out_size)
{
    const float* X    = (const float*)d_in[0];
    const float* mask = (const float*)d_in[1];
    const float* Wq   = (const float*)d_in[2];
    const float* bq   = (const float*)d_in[3];
    const float* Wk   = (const float*)d_in[4];
    const float* bk   = (const float*)d_in[5];
    const float* Wv   = (const float*)d_in[6];
    const float* bv   = (const float*)d_in[7];
    float* out = (float*)d_out;

    cudaFuncSetAttribute(attn_kernel, cudaFuncAttributeMaxDynamicSharedMemorySize, ATTN_SMEM);

    dim3 gg(8192 / 128, HH / 128, 3);
    qkv_gemm_kernel<<<gg, 256>>>(X, Wq, bq, Wk, bk, Wv, bv);

    dim3 ga(SS / 128, BH);
    attn_kernel<<<ga, 256, ATTN_SMEM>>>(mask, out);
}

// round 6
// speedup vs baseline: 1.2141x; 1.1013x over previous
#include <cuda_runtime.h>
#include <cstdint>

#define BB 4
#define SS 2048
#define HH 1024
#define HDD 64
#define BH 64

// Scratch. Q (scaled 0.125),K head-major [B*NH][S][HD] with hd paired-permuted;
// V transposed [B*NH][HD][S] with key-dim paired-permuted. All tf32-rounded.
__device__ float g_q[BB*SS*HH];
__device__ float g_k[BB*SS*HH];
__device__ float g_v[BB*SS*HH];
// Pre-rounded, column-paired GEMM inputs
__device__ float g_xr[BB*SS*HH];
__device__ float g_wq[HH*HH];
__device__ float g_wk[HH*HH];
__device__ float g_wv[HH*HH];

__device__ __forceinline__ float tf32r(float x) {
    uint32_t r;
    asm("cvt.rna.tf32.f32 %0, %1;" : "=r"(r) : "f"(x));
    return __uint_as_float(r);
}
__device__ __forceinline__ uint32_t fb(float x) { return __float_as_uint(x); }
__device__ __forceinline__ int perm8(int c) { return ((c & 3) << 1) | ((c >> 2) & 1); }

__device__ __forceinline__ void mma8(float c[4],
                                     uint32_t a0, uint32_t a1, uint32_t a2, uint32_t a3,
                                     uint32_t b0, uint32_t b1) {
    asm volatile(
        "mma.sync.aligned.m16n8k8.row.col.f32.tf32.tf32.f32 "
        "{%0,%1,%2,%3},{%4,%5,%6,%7},{%8,%9},{%0,%1,%2,%3};\n"
        : "+f"(c[0]), "+f"(c[1]), "+f"(c[2]), "+f"(c[3])
        : "r"(a0), "r"(a1), "r"(a2), "r"(a3), "r"(b0), "r"(b1));
}

__device__ __forceinline__ void cpasync16(uint32_t dst_smem, const void* src) {
    asm volatile("cp.async.cg.shared.global [%0], [%1], 16;\n"
                 :: "r"(dst_smem), "l"(src));
}
__device__ __forceinline__ void cpcommit() { asm volatile("cp.async.commit_group;\n"); }
__device__ __forceinline__ void cpwait0()  { asm volatile("cp.async.wait_group 0;\n"); }

// ======================= Pre-round + pair-permute X and W =======================
// Per 8-col group: out positions [c0,c4,c1,c5,c2,c6,c3,c7], tf32-rounded.
#define XGRP (BB*SS*HH/8)
#define WGRP (HH*HH/8)
__global__ __launch_bounds__(256) void preround_kernel(
    const float* __restrict__ X, const float* __restrict__ Wq,
    const float* __restrict__ Wk, const float* __restrict__ Wv)
{
    int gid = blockIdx.x * 256 + threadIdx.x;
    const float* src; float* dst; int off;
    if (gid < XGRP) { src = X; dst = g_xr; off = gid * 8; }
    else {
        int w = gid - XGRP;
        int which = w / WGRP, rem = w % WGRP;
        off = rem * 8;
        if (which == 0)      { src = Wq; dst = g_wq; }
        else if (which == 1) { src = Wk; dst = g_wk; }
        else                 { src = Wv; dst = g_wv; }
    }
    float4 a = *(const float4*)&src[off];
    float4 b = *(const float4*)&src[off + 4];
    *(float4*)&dst[off]     = make_float4(tf32r(a.x), tf32r(b.x), tf32r(a.y), tf32r(b.y));
    *(float4*)&dst[off + 4] = make_float4(tf32r(a.z), tf32r(b.z), tf32r(a.w), tf32r(b.w));
}

// ======================= QKV projection GEMM =======================
// Inputs pre-rounded & paired -> cp.async fills, LDS.64 fragments, 2-stage pipe.
#define GSTR 40
#define GTILE (128 * GSTR)
#define GEMM_SMEM (4 * GTILE * (int)sizeof(float))

__global__ __launch_bounds__(256) void qkv_gemm_kernel(
    const float* __restrict__ bq, const float* __restrict__ bk,
    const float* __restrict__ bv)
{
    extern __shared__ float gs[];

    const float* W; const float* bias; float* out;
    if (blockIdx.z == 0)      { W = g_wq; bias = bq; out = g_q; }
    else if (blockIdx.z == 1) { W = g_wk; bias = bk; out = g_k; }
    else                      { W = g_wv; bias = bv; out = g_v; }
    const bool vtrans = (blockIdx.z == 2);
    const float oscale = (blockIdx.z == 0) ? 0.125f : 1.0f;

    const int m0 = blockIdx.x * 128;
    const int n0 = blockIdx.y * 128;
    const int tid = threadIdx.x;
    const int lane = tid & 31, warp = tid >> 5;
    const int wm = warp >> 2, wn = warp & 3;
    const int g = lane >> 2, tg = lane & 3;
    const uint32_t sbase = (uint32_t)__cvta_generic_to_shared(gs);
    const float* Xr = g_xr;

    float acc[4][4][4];
    #pragma unroll
    for (int mt = 0; mt < 4; mt++)
        #pragma unroll
        for (int nt = 0; nt < 4; nt++)
            #pragma unroll
            for (int j = 0; j < 4; j++) acc[mt][nt][j] = 0.f;

    // stage s: A at s*GTILE, B at (2+s)*GTILE
    {
        #pragma unroll
        for (int i = 0; i < 4; i++) {
            int c = tid + i * 256;
            int row = c >> 3, c4 = (c & 7) * 4;
            cpasync16(sbase + (row * GSTR + c4) * 4,
                      &Xr[(size_t)(m0 + row) * HH + c4]);
            cpasync16(sbase + (2 * GTILE + row * GSTR + c4) * 4,
                      &W[(size_t)(n0 + row) * HH + c4]);
        }
        cpcommit();
    }

    for (int t = 0; t < 32; t++) {
        const int cur = t & 1;
        cpwait0();
        __syncthreads();

        if (t + 1 < 32) {
            const int nxt = cur ^ 1;
            const int k0 = (t + 1) * 32;
            #pragma unroll
            for (int i = 0; i < 4; i++) {
                int c = tid + i * 256;
                int row = c >> 3, c4 = (c & 7) * 4;
                cpasync16(sbase + (nxt * GTILE + row * GSTR + c4) * 4,
                          &Xr[(size_t)(m0 + row) * HH + k0 + c4]);
                cpasync16(sbase + ((2 + nxt) * GTILE + row * GSTR + c4) * 4,
                          &W[(size_t)(n0 + row) * HH + k0 + c4]);
            }
            cpcommit();
        }

        float* As = gs + cur * GTILE;
        float* Bs = gs + (2 + cur) * GTILE;

        #pragma unroll
        for (int ks = 0; ks < 4; ks++) {
            float2 a_[4][2];
            #pragma unroll
            for (int mt = 0; mt < 4; mt++) {
                int r = wm * 64 + mt * 16 + g;
                a_[mt][0] = *(const float2*)&As[r * GSTR + ks * 8 + 2 * tg];
                a_[mt][1] = *(const float2*)&As[(r + 8) * GSTR + ks * 8 + 2 * tg];
            }
            #pragma unroll
            for (int nt = 0; nt < 4; nt++) {
                int n = wn * 32 + nt * 8 + g;
                float2 bv2 = *(const float2*)&Bs[n * GSTR + ks * 8 + 2 * tg];
                #pragma unroll
                for (int mt = 0; mt < 4; mt++)
                    mma8(acc[mt][nt],
                         fb(a_[mt][0].x), fb(a_[mt][1].x),
                         fb(a_[mt][0].y), fb(a_[mt][1].y),
                         fb(bv2.x), fb(bv2.y));
            }
        }
    }
    __syncthreads();

    // Epilogue: bias + tf32 round + scatter with pair-permutation.
    #pragma unroll
    for (int mt = 0; mt < 4; mt++) {
        int r = m0 + wm * 64 + mt * 16 + g;
        int b_  = r >> 11, s_ = r & 2047;
        int b8_ = (r + 8) >> 11, s8_ = (r + 8) & 2047;
        #pragma unroll
        for (int nt = 0; nt < 4; nt++) {
            int c = n0 + wn * 32 + nt * 8 + 2 * tg;
            int nh = (c >> 6) & 15, hd = c & 63;
            float bi0 = bias[c], bi1 = bias[c + 1];
            int h0 = (b_  << 4) + nh;
            int h8 = (b8_ << 4) + nh;
            float v0 = tf32r((acc[mt][nt][0] + bi0) * oscale);
            float v1 = tf32r((acc[mt][nt][1] + bi1) * oscale);
            float v2 = tf32r((acc[mt][nt][2] + bi0) * oscale);
            float v3 = tf32r((acc[mt][nt][3] + bi1) * oscale);
            if (vtrans) {
                // V^T [head][hd][s], key-dim (s) pair-permuted within 8
                int sp0 = (s_  & ~7) | perm8(s_  & 7);
                int sp8 = (s8_ & ~7) | perm8(s8_ & 7);
                int t0 = (h0 * HDD + hd) * SS + sp0;
                int t8 = (h8 * HDD + hd) * SS + sp8;
                out[t0]      = v0;
                out[t0 + SS] = v1;
                out[t8]      = v2;
                out[t8 + SS] = v3;
            } else {
                // Q/K [head][s][hd], hd pair-permuted within 8
                int l = hd & 7;
                int p0 = (hd & ~7) | perm8(l);
                int p1 = (hd & ~7) | perm8(l + 1);
                int base0 = (h0 * SS + s_ ) * HDD;
                int base8 = (h8 * SS + s8_) * HDD;
                out[base0 + p0] = v0;
                out[base0 + p1] = v1;
                out[base8 + p0] = v2;
                out[base8 + p1] = v3;
            }
        }
    }
}

// ======================= Flash attention =======================
// 8 warps, 128 q-rows. Double-buffered cp.async K/V tiles. Paired columns:
// every B fragment (and Q) is one LDS.64/LDG.64, conflict-free (stride 72).
#define KSTR 72
#define TILE_F (64 * KSTR)
#define ATTN_SMEM ((4 * TILE_F + SS) * (int)sizeof(float))

__global__ __launch_bounds__(256, 2) void attn_kernel(const float* __restrict__ mask,
                                                      float* __restrict__ out)
{
    extern __shared__ float sm[];
    float* Msk = sm + 4 * TILE_F;

    const int tid = threadIdx.x;
    const int lane = tid & 31, warp = tid >> 5;
    const int g = lane >> 2, tg = lane & 3;
    const int hbh = blockIdx.y;
    const int b = hbh >> 4, nh = hbh & 15;
    const int q0 = blockIdx.x * 128;
    const int r0 = warp * 16;

    const float* qb  = g_q + ((size_t)hbh * SS + q0) * HDD;
    const float* kb  = g_k + (size_t)hbh * SS * HDD;
    const float* vtb = g_v + (size_t)hbh * HDD * SS;

    {
        const float* mrow = mask + b * SS;
        #pragma unroll
        for (int i = 0; i < 2; i++) {
            int idx = tid + i * 256;
            *(float4*)&Msk[idx * 4] = *(const float4*)&mrow[idx * 4];
        }
    }

    // Q fragments (hd pair-permuted in gmem -> LDG.64 per pair)
    uint32_t qa[8][4];
    #pragma unroll
    for (int ks = 0; ks < 8; ks++) {
        float2 q0v = *(const float2*)&qb[(r0 + g)     * 64 + ks * 8 + 2 * tg];
        float2 q1v = *(const float2*)&qb[(r0 + 8 + g) * 64 + ks * 8 + 2 * tg];
        qa[ks][0] = fb(q0v.x); qa[ks][1] = fb(q1v.x);
        qa[ks][2] = fb(q0v.y); qa[ks][3] = fb(q1v.y);
    }

    const uint32_t smem_base = (uint32_t)__cvta_generic_to_shared(sm);

    float O[8][4];
    #pragma unroll
    for (int nt = 0; nt < 8; nt++)
        #pragma unroll
        for (int j = 0; j < 4; j++) O[nt][j] = 0.f;
    float m0s = -1e30f, m1s = -1e30f, l0 = 0.f, l1 = 0.f;

    const int srcA = (lane & ~3) | (tg >> 1);
    const int srcB = srcA + 2;
    const bool odd = (tg & 1);

    {
        #pragma unroll
        for (int i = 0; i < 4; i++) {
            int c = tid + i * 256;
            int row = c >> 4, c4 = (c & 15) * 4;
            cpasync16(smem_base + (row * KSTR + c4) * 4, &kb[row * 64 + c4]);
            cpasync16(smem_base + (2 * TILE_F + row * KSTR + c4) * 4,
                      &vtb[(size_t)row * SS + c4]);
        }
        cpcommit();
    }

    for (int kt = 0; kt < 32; kt++) {
        const int cur = kt & 1;
        float* Ks = sm + cur * TILE_F;
        float* Vt = sm + 2 * TILE_F + cur * TILE_F;

        cpwait0();
        __syncthreads();

        if (kt + 1 < 32) {
            const int nxt = (kt + 1) & 1;
            const int koff = (kt + 1) * 64;
            #pragma unroll
            for (int i = 0; i < 4; i++) {
                int c = tid + i * 256;
                int row = c >> 4, c4 = (c & 15) * 4;
                cpasync16(smem_base + (nxt * TILE_F + row * KSTR + c4) * 4,
                          &kb[(koff + row) * 64 + c4]);
                cpasync16(smem_base + ((2 + nxt) * TILE_F + row * KSTR + c4) * 4,
                          &vtb[(size_t)row * SS + koff + c4]);
            }
            cpcommit();
        }

        // S = Q K^T (LDS.64 B fragments)
        float s[8][4];
        #pragma unroll
        for (int nt = 0; nt < 8; nt++)
            #pragma unroll
            for (int j = 0; j < 4; j++) s[nt][j] = 0.f;

        #pragma unroll
        for (int ks = 0; ks < 8; ks++) {
            #pragma unroll
            for (int nt = 0; nt < 8; nt++) {
                float2 kk = *(const float2*)&Ks[(nt * 8 + g) * KSTR + ks * 8 + 2 * tg];
                mma8(s[nt], qa[ks][0], qa[ks][1], qa[ks][2], qa[ks][3],
                     fb(kk.x), fb(kk.y));
            }
        }

        const float* Mt = Msk + kt * 64;
        float mx0 = -1e30f, mx1 = -1e30f;
        #pragma unroll
        for (int nt = 0; nt < 8; nt++) {
            float mk0 = Mt[nt * 8 + 2 * tg], mk1 = Mt[nt * 8 + 2 * tg + 1];
            s[nt][0] += mk0; s[nt][1] += mk1; s[nt][2] += mk0; s[nt][3] += mk1;
            mx0 = fmaxf(mx0, fmaxf(s[nt][0], s[nt][1]));
            mx1 = fmaxf(mx1, fmaxf(s[nt][2], s[nt][3]));
        }
        mx0 = fmaxf(mx0, __shfl_xor_sync(0xffffffffu, mx0, 1));
        mx0 = fmaxf(mx0, __shfl_xor_sync(0xffffffffu, mx0, 2));
        mx1 = fmaxf(mx1, __shfl_xor_sync(0xffffffffu, mx1, 1));
        mx1 = fmaxf(mx1, __shfl_xor_sync(0xffffffffu, mx1, 2));

        float mn0 = fmaxf(m0s, mx0), mn1 = fmaxf(m1s, mx1);
        float al0 = __expf(m0s - mn0), al1 = __expf(m1s - mn1);
        m0s = mn0; m1s = mn1;

        float ls0 = 0.f, ls1 = 0.f;
        #pragma unroll
        for (int nt = 0; nt < 8; nt++) {
            float p0 = __expf(s[nt][0] - mn0);
            float p1 = __expf(s[nt][1] - mn0);
            float p2 = __expf(s[nt][2] - mn1);
            float p3 = __expf(s[nt][3] - mn1);
            ls0 += p0 + p1; ls1 += p2 + p3;
            s[nt][0] = tf32r(p0); s[nt][1] = tf32r(p1);
            s[nt][2] = tf32r(p2); s[nt][3] = tf32r(p3);
        }
        ls0 += __shfl_xor_sync(0xffffffffu, ls0, 1);
        ls0 += __shfl_xor_sync(0xffffffffu, ls0, 2);
        ls1 += __shfl_xor_sync(0xffffffffu, ls1, 1);
        ls1 += __shfl_xor_sync(0xffffffffu, ls1, 2);
        l0 = l0 * al0 + ls0;
        l1 = l1 * al1 + ls1;

        #pragma unroll
        for (int nt = 0; nt < 8; nt++) {
            O[nt][0] *= al0; O[nt][1] *= al0; O[nt][2] *= al1; O[nt][3] *= al1;
        }

        // O += P V (shuffle P -> A layout; LDS.64 V fragments)
        #pragma unroll
        for (int ks = 0; ks < 8; ks++) {
            float x0 = __shfl_sync(0xffffffffu, s[ks][0], srcA);
            float x1 = __shfl_sync(0xffffffffu, s[ks][1], srcA);
            float y0 = __shfl_sync(0xffffffffu, s[ks][0], srcB);
            float y1 = __shfl_sync(0xffffffffu, s[ks][1], srcB);
            float z0 = __shfl_sync(0xffffffffu, s[ks][2], srcA);
            float z1 = __shfl_sync(0xffffffffu, s[ks][3], srcA);
            float w0 = __shfl_sync(0xffffffffu, s[ks][2], srcB);
            float w1 = __shfl_sync(0xffffffffu, s[ks][3], srcB);
            uint32_t a0 = fb(odd ? x1 : x0);
            uint32_t a2 = fb(odd ? y1 : y0);
            uint32_t a1 = fb(odd ? z1 : z0);
            uint32_t a3 = fb(odd ? w1 : w0);
            #pragma unroll
            for (int nt = 0; nt < 8; nt++) {
                float2 vv = *(const float2*)&Vt[(nt * 8 + g) * KSTR + ks * 8 + 2 * tg];
                mma8(O[nt], a0, a1, a2, a3, fb(vv.x), fb(vv.y));
            }
        }
    }

    float i0 = 1.f / l0, i1 = 1.f / l1;
    int rg  = q0 + r0 + g;
    int rg8 = rg + 8;
    #pragma unroll
    for (int nt = 0; nt < 8; nt++) {
        int hd = nt * 8 + 2 * tg;
        int o0 = (b * SS + rg ) * HH + nh * 64 + hd;
        int o8 = (b * SS + rg8) * HH + nh * 64 + hd;
        out[o0]     = O[nt][0] * i0;
        out[o0 + 1] = O[nt][1] * i0;
        out[o8]     = O[nt][2] * i1;
        out[o8 + 1] = O[nt][3] * i1;
    }
}

extern "C" void kernel_launch(void* const* d_in, const int* in_sizes, int n_in,
                              void* d_out, int out_size)
{
    const float* X    = (const float*)d_in[0];
    const float* mask = (const float*)d_in[1];
    const float* Wq   = (const float*)d_in[2];
    const float* bq   = (const float*)d_in[3];
    const float* Wk   = (const float*)d_in[4];
    const float* bk   = (const float*)d_in[5];
    const float* Wv   = (const float*)d_in[6];
    const float* bv   = (const float*)d_in[7];
    float* out = (float*)d_out;

    cudaFuncSetAttribute(qkv_gemm_kernel, cudaFuncAttributeMaxDynamicSharedMemorySize, GEMM_SMEM);
    cudaFuncSetAttribute(attn_kernel, cudaFuncAttributeMaxDynamicSharedMemorySize, ATTN_SMEM);

    int total_groups = XGRP + 3 * WGRP;
    preround_kernel<<<total_groups / 256, 256>>>(X, Wq, Wk, Wv);

    dim3 gg(8192 / 128, HH / 128, 3);
    qkv_gemm_kernel<<<gg, 256, GEMM_SMEM>>>(bq, bk, bv);

    dim3 ga(SS / 128, BH);
    attn_kernel<<<ga, 256, ATTN_SMEM>>>(mask, out);
}

// round 8
// speedup vs baseline: 1.2579x; 1.0361x over previous
#include <cuda_runtime.h>
#include <cstdint>

#define BB 4
#define SS 2048
#define HH 1024
#define HDD 64
#define BH 64

// Scratch, all tf32-rounded by producers:
// Q [B*NH][S][HD], hd pair-permuted, pre-scaled 0.125
// K [B*NH][S][HD], hd pair-permuted AND s(key) perm8-permuted within 8-groups
// V transposed [B*NH][HD][S], key-dim perm8-permuted within 8-groups
__device__ float g_q[BB*SS*HH];
__device__ float g_k[BB*SS*HH];
__device__ float g_v[BB*SS*HH];
// Pre-rounded, column-paired GEMM inputs
__device__ float g_xr[BB*SS*HH];
__device__ float g_wq[HH*HH];
__device__ float g_wk[HH*HH];
__device__ float g_wv[HH*HH];

__device__ __forceinline__ float tf32r(float x) {
    uint32_t r;
    asm("cvt.rna.tf32.f32 %0, %1;" : "=r"(r) : "f"(x));
    return __uint_as_float(r);
}
__device__ __forceinline__ uint32_t fb(float x) { return __float_as_uint(x); }
__device__ __forceinline__ int perm8(int c) { return ((c & 3) << 1) | ((c >> 2) & 1); }

__device__ __forceinline__ void mma8(float c[4],
                                     uint32_t a0, uint32_t a1, uint32_t a2, uint32_t a3,
                                     uint32_t b0, uint32_t b1) {
    asm volatile(
        "mma.sync.aligned.m16n8k8.row.col.f32.tf32.tf32.f32 "
        "{%0,%1,%2,%3},{%4,%5,%6,%7},{%8,%9},{%0,%1,%2,%3};\n"
        : "+f"(c[0]), "+f"(c[1]), "+f"(c[2]), "+f"(c[3])
        : "r"(a0), "r"(a1), "r"(a2), "r"(a3), "r"(b0), "r"(b1));
}

__device__ __forceinline__ void cpasync16(uint32_t dst_smem, const void* src) {
    asm volatile("cp.async.cg.shared.global [%0], [%1], 16;\n"
                 :: "r"(dst_smem), "l"(src));
}
__device__ __forceinline__ void cpcommit() { asm volatile("cp.async.commit_group;\n"); }
__device__ __forceinline__ void cpwait0()  { asm volatile("cp.async.wait_group 0;\n"); }

// ======================= Pre-round + pair-permute X and W =======================
#define XGRP (BB*SS*HH/8)
#define WGRP (HH*HH/8)
__global__ __launch_bounds__(256) void preround_kernel(
    const float* __restrict__ X, const float* __restrict__ Wq,
    const float* __restrict__ Wk, const float* __restrict__ Wv)
{
    int gid = blockIdx.x * 256 + threadIdx.x;
    const float* src; float* dst; int off;
    if (gid < XGRP) { src = X; dst = g_xr; off = gid * 8; }
    else {
        int w = gid - XGRP;
        int which = w / WGRP, rem = w % WGRP;
        off = rem * 8;
        if (which == 0)      { src = Wq; dst = g_wq; }
        else if (which == 1) { src = Wk; dst = g_wk; }
        else                 { src = Wv; dst = g_wv; }
    }
    float4 a = *(const float4*)&src[off];
    float4 b = *(const float4*)&src[off + 4];
    *(float4*)&dst[off]     = make_float4(tf32r(a.x), tf32r(b.x), tf32r(a.y), tf32r(b.y));
    *(float4*)&dst[off + 4] = make_float4(tf32r(a.z), tf32r(b.z), tf32r(a.w), tf32r(b.w));
}

// ======================= QKV projection GEMM =======================
// Inputs pre-rounded & paired -> cp.async fills, LDS.64 fragments, 2-stage pipe.
#define GSTR 40
#define GTILE (128 * GSTR)
#define GEMM_SMEM (4 * GTILE * (int)sizeof(float))

__global__ __launch_bounds__(256) void qkv_gemm_kernel(
    const float* __restrict__ bq, const float* __restrict__ bk,
    const float* __restrict__ bv)
{
    extern __shared__ float gs[];

    const float* W; const float* bias; float* out;
    if (blockIdx.z == 0)      { W = g_wq; bias = bq; out = g_q; }
    else if (blockIdx.z == 1) { W = g_wk; bias = bk; out = g_k; }
    else                      { W = g_wv; bias = bv; out = g_v; }
    const bool vtrans = (blockIdx.z == 2);
    const bool kperm  = (blockIdx.z == 1);
    const float oscale = (blockIdx.z == 0) ? 0.125f : 1.0f;

    const int m0 = blockIdx.x * 128;
    const int n0 = blockIdx.y * 128;
    const int tid = threadIdx.x;
    const int lane = tid & 31, warp = tid >> 5;
    const int wm = warp >> 2, wn = warp & 3;
    const int g = lane >> 2, tg = lane & 3;
    const uint32_t sbase = (uint32_t)__cvta_generic_to_shared(gs);
    const float* Xr = g_xr;

    float acc[4][4][4];
    #pragma unroll
    for (int mt = 0; mt < 4; mt++)
        #pragma unroll
        for (int nt = 0; nt < 4; nt++)
            #pragma unroll
            for (int j = 0; j < 4; j++) acc[mt][nt][j] = 0.f;

    {
        #pragma unroll
        for (int i = 0; i < 4; i++) {
            int c = tid + i * 256;
            int row = c >> 3, c4 = (c & 7) * 4;
            cpasync16(sbase + (row * GSTR + c4) * 4,
                      &Xr[(size_t)(m0 + row) * HH + c4]);
            cpasync16(sbase + (2 * GTILE + row * GSTR + c4) * 4,
                      &W[(size_t)(n0 + row) * HH + c4]);
        }
        cpcommit();
    }

    for (int t = 0; t < 32; t++) {
        const int cur = t & 1;
        cpwait0();
        __syncthreads();

        if (t + 1 < 32) {
            const int nxt = cur ^ 1;
            const int k0 = (t + 1) * 32;
            #pragma unroll
            for (int i = 0; i < 4; i++) {
                int c = tid + i * 256;
                int row = c >> 3, c4 = (c & 7) * 4;
                cpasync16(sbase + (nxt * GTILE + row * GSTR + c4) * 4,
                          &Xr[(size_t)(m0 + row) * HH + k0 + c4]);
                cpasync16(sbase + ((2 + nxt) * GTILE + row * GSTR + c4) * 4,
                          &W[(size_t)(n0 + row) * HH + k0 + c4]);
            }
            cpcommit();
        }

        float* As = gs + cur * GTILE;
        float* Bs = gs + (2 + cur) * GTILE;

        #pragma unroll
        for (int ks = 0; ks < 4; ks++) {
            float2 a_[4][2];
            #pragma unroll
            for (int mt = 0; mt < 4; mt++) {
                int r = wm * 64 + mt * 16 + g;
                a_[mt][0] = *(const float2*)&As[r * GSTR + ks * 8 + 2 * tg];
                a_[mt][1] = *(const float2*)&As[(r + 8) * GSTR + ks * 8 + 2 * tg];
            }
            #pragma unroll
            for (int nt = 0; nt < 4; nt++) {
                int n = wn * 32 + nt * 8 + g;
                float2 bv2 = *(const float2*)&Bs[n * GSTR + ks * 8 + 2 * tg];
                #pragma unroll
                for (int mt = 0; mt < 4; mt++)
                    mma8(acc[mt][nt],
                         fb(a_[mt][0].x), fb(a_[mt][1].x),
                         fb(a_[mt][0].y), fb(a_[mt][1].y),
                         fb(bv2.x), fb(bv2.y));
            }
        }
    }
    __syncthreads();

    // Epilogue: bias + tf32 round + scatter with pair/key permutations.
    #pragma unroll
    for (int mt = 0; mt < 4; mt++) {
        int r = m0 + wm * 64 + mt * 16 + g;
        int b_  = r >> 11, s_ = r & 2047;
        int b8_ = (r + 8) >> 11, s8_ = (r + 8) & 2047;
        #pragma unroll
        for (int nt = 0; nt < 4; nt++) {
            int c = n0 + wn * 32 + nt * 8 + 2 * tg;
            int nh = (c >> 6) & 15, hd = c & 63;
            float bi0 = bias[c], bi1 = bias[c + 1];
            int h0 = (b_  << 4) + nh;
            int h8 = (b8_ << 4) + nh;
            float v0 = tf32r((acc[mt][nt][0] + bi0) * oscale);
            float v1 = tf32r((acc[mt][nt][1] + bi1) * oscale);
            float v2 = tf32r((acc[mt][nt][2] + bi0) * oscale);
            float v3 = tf32r((acc[mt][nt][3] + bi1) * oscale);
            if (vtrans) {
                // V^T [head][hd][s], key-dim (s) pair-permuted within 8
                int sp0 = (s_  & ~7) | perm8(s_  & 7);
                int sp8 = (s8_ & ~7) | perm8(s8_ & 7);
                int t0 = (h0 * HDD + hd) * SS + sp0;
                int t8 = (h8 * HDD + hd) * SS + sp8;
                out[t0]      = v0;
                out[t0 + SS] = v1;
                out[t8]      = v2;
                out[t8 + SS] = v3;
            } else {
                // Q/K [head][s][hd], hd pair-permuted within 8.
                // K additionally: s (key) perm8-permuted within 8-groups, so the
                // attention S-accumulator lands directly in PV A-operand layout.
                int l = hd & 7;
                int p0 = (hd & ~7) | perm8(l);
                int p1 = (hd & ~7) | perm8(l + 1);
                int so_ = s_, so8 = s8_;
                if (kperm) {
                    so_ = (s_  & ~7) | perm8(s_  & 7);
                    so8 = (s8_ & ~7) | perm8(s8_ & 7);
                }
                int base0 = (h0 * SS + so_) * HDD;
                int base8 = (h8 * SS + so8) * HDD;
                out[base0 + p0] = v0;
                out[base0 + p1] = v1;
                out[base8 + p0] = v2;
                out[base8 + p1] = v3;
            }
        }
    }
}

// ======================= Flash attention =======================
// 8 warps, 128 q-rows. Double-buffered cp.async K/V tiles. Keys arrive
// perm8-permuted (from scratch layout), so the S accumulator IS the PV
// A-operand (register renaming, zero shuffles). Mask permuted at CTA start.
#define KSTR 72
#define TILE_F (64 * KSTR)
#define ATTN_SMEM ((4 * TILE_F + SS) * (int)sizeof(float))

__global__ __launch_bounds__(256, 2) void attn_kernel(const float* __restrict__ mask,
                                                      float* __restrict__ out)
{
    extern __shared__ float sm[];
    float* Msk = sm + 4 * TILE_F;

    const int tid = threadIdx.x;
    const int lane = tid & 31, warp = tid >> 5;
    const int g = lane >> 2, tg = lane & 3;
    const int hbh = blockIdx.y;
    const int b = hbh >> 4, nh = hbh & 15;
    const int q0 = blockIdx.x * 128;
    const int r0 = warp * 16;

    const float* qb  = g_q + ((size_t)hbh * SS + q0) * HDD;
    const float* kb  = g_k + (size_t)hbh * SS * HDD;
    const float* vtb = g_v + (size_t)hbh * HDD * SS;

    // Mask preload, perm8-permuted within 8-groups to match key order in S.
    {
        const float* mrow = mask + b * SS;
        #pragma unroll
        for (int i = 0; i < 8; i++) {
            int idx = tid + i * 256;
            Msk[(idx & ~7) | perm8(idx & 7)] = mrow[idx];
        }
    }

    // Q fragments (hd pair-permuted in gmem -> LDG.64 per pair)
    uint32_t qa[8][4];
    #pragma unroll
    for (int ks = 0; ks < 8; ks++) {
        float2 q0v = *(const float2*)&qb[(r0 + g)     * 64 + ks * 8 + 2 * tg];
        float2 q1v = *(const float2*)&qb[(r0 + 8 + g) * 64 + ks * 8 + 2 * tg];
        qa[ks][0] = fb(q0v.x); qa[ks][1] = fb(q1v.x);
        qa[ks][2] = fb(q0v.y); qa[ks][3] = fb(q1v.y);
    }

    const uint32_t smem_base = (uint32_t)__cvta_generic_to_shared(sm);

    float O[8][4];
    #pragma unroll
    for (int nt = 0; nt < 8; nt++)
        #pragma unroll
        for (int j = 0; j < 4; j++) O[nt][j] = 0.f;
    float m0s = -1e30f, m1s = -1e30f, l0 = 0.f, l1 = 0.f;

    {
        #pragma unroll
        for (int i = 0; i < 4; i++) {
            int c = tid + i * 256;
            int row = c >> 4, c4 = (c & 15) * 4;
            cpasync16(smem_base + (row * KSTR + c4) * 4, &kb[row * 64 + c4]);
            cpasync16(smem_base + (2 * TILE_F + row * KSTR + c4) * 4,
                      &vtb[(size_t)row * SS + c4]);
        }
        cpcommit();
    }

    for (int kt = 0; kt < 32; kt++) {
        const int cur = kt & 1;
        float* Ks = sm + cur * TILE_F;
        float* Vt = sm + 2 * TILE_F + cur * TILE_F;

        cpwait0();
        __syncthreads();

        if (kt + 1 < 32) {
            const int nxt = (kt + 1) & 1;
            const int koff = (kt + 1) * 64;
            #pragma unroll
            for (int i = 0; i < 4; i++) {
                int c = tid + i * 256;
                int row = c >> 4, c4 = (c & 15) * 4;
                cpasync16(smem_base + (nxt * TILE_F + row * KSTR + c4) * 4,
                          &kb[(koff + row) * 64 + c4]);
                cpasync16(smem_base + ((2 + nxt) * TILE_F + row * KSTR + c4) * 4,
                          &vtb[(size_t)row * SS + koff + c4]);
            }
            cpcommit();
        }

        // S = Q K^T (LDS.64 B fragments; S cols are perm8-keys)
        float s[8][4];
        #pragma unroll
        for (int nt = 0; nt < 8; nt++)
            #pragma unroll
            for (int j = 0; j < 4; j++) s[nt][j] = 0.f;

        #pragma unroll
        for (int ks = 0; ks < 8; ks++) {
            #pragma unroll
            for (int nt = 0; nt < 8; nt++) {
                float2 kk = *(const float2*)&Ks[(nt * 8 + g) * KSTR + ks * 8 + 2 * tg];
                mma8(s[nt], qa[ks][0], qa[ks][1], qa[ks][2], qa[ks][3],
                     fb(kk.x), fb(kk.y));
            }
        }

        const float* Mt = Msk + kt * 64;
        float mx0 = -1e30f, mx1 = -1e30f;
        #pragma unroll
        for (int nt = 0; nt < 8; nt++) {
            float mk0 = Mt[nt * 8 + 2 * tg], mk1 = Mt[nt * 8 + 2 * tg + 1];
            s[nt][0] += mk0; s[nt][1] += mk1; s[nt][2] += mk0; s[nt][3] += mk1;
            mx0 = fmaxf(mx0, fmaxf(s[nt][0], s[nt][1]));
            mx1 = fmaxf(mx1, fmaxf(s[nt][2], s[nt][3]));
        }
        mx0 = fmaxf(mx0, __shfl_xor_sync(0xffffffffu, mx0, 1));
        mx0 = fmaxf(mx0, __shfl_xor_sync(0xffffffffu, mx0, 2));
        mx1 = fmaxf(mx1, __shfl_xor_sync(0xffffffffu, mx1, 1));
        mx1 = fmaxf(mx1, __shfl_xor_sync(0xffffffffu, mx1, 2));

        float mn0 = fmaxf(m0s, mx0), mn1 = fmaxf(m1s, mx1);
        float al0 = __expf(m0s - mn0), al1 = __expf(m1s - mn1);
        m0s = mn0; m1s = mn1;

        float ls0 = 0.f, ls1 = 0.f;
        #pragma unroll
        for (int nt = 0; nt < 8; nt++) {
            float p0 = __expf(s[nt][0] - mn0);
            float p1 = __expf(s[nt][1] - mn0);
            float p2 = __expf(s[nt][2] - mn1);
            float p3 = __expf(s[nt][3] - mn1);
            ls0 += p0 + p1; ls1 += p2 + p3;
            s[nt][0] = tf32r(p0); s[nt][1] = tf32r(p1);
            s[nt][2] = tf32r(p2); s[nt][3] = tf32r(p3);
        }
        ls0 += __shfl_xor_sync(0xffffffffu, ls0, 1);
        ls0 += __shfl_xor_sync(0xffffffffu, ls0, 2);
        ls1 += __shfl_xor_sync(0xffffffffu, ls1, 1);
        ls1 += __shfl_xor_sync(0xffffffffu, ls1, 2);
        l0 = l0 * al0 + ls0;
        l1 = l1 * al1 + ls1;

        #pragma unroll
        for (int nt = 0; nt < 8; nt++) {
            O[nt][0] *= al0; O[nt][1] *= al0; O[nt][2] *= al1; O[nt][3] *= al1;
        }

        // O += P V : S accumulator (perm8 key cols) == PV A-operand.
        // A = (c0, c2, c1, c3). Zero shuffles.
        #pragma unroll
        for (int ks = 0; ks < 8; ks++) {
            uint32_t a0 = fb(s[ks][0]);
            uint32_t a1 = fb(s[ks][2]);
            uint32_t a2 = fb(s[ks][1]);
            uint32_t a3 = fb(s[ks][3]);
            #pragma unroll
            for (int nt = 0; nt < 8; nt++) {
                float2 vv = *(const float2*)&Vt[(nt * 8 + g) * KSTR + ks * 8 + 2 * tg];
                mma8(O[nt], a0, a1, a2, a3, fb(vv.x), fb(vv.y));
            }
        }
    }

    float i0 = 1.f / l0, i1 = 1.f / l1;
    int rg  = q0 + r0 + g;
    int rg8 = rg + 8;
    #pragma unroll
    for (int nt = 0; nt < 8; nt++) {
        int hd = nt * 8 + 2 * tg;
        int o0 = (b * SS + rg ) * HH + nh * 64 + hd;
        int o8 = (b * SS + rg8) * HH + nh * 64 + hd;
        out[o0]     = O[nt][0] * i0;
        out[o0 + 1] = O[nt][1] * i0;
        out[o8]     = O[nt][2] * i1;
        out[o8 + 1] = O[nt][3] * i1;
    }
}

extern "C" void kernel_launch(void* const* d_in, const int* in_sizes, int n_in,
                              void* d_out, int out_size)
{
    const float* X    = (const float*)d_in[0];
    const float* mask = (const float*)d_in[1];
    const float* Wq   = (const float*)d_in[2];
    const float* bq   = (const float*)d_in[3];
    const float* Wk   = (const float*)d_in[4];
    const float* bk   = (const float*)d_in[5];
    const float* Wv   = (const float*)d_in[6];
    const float* bv   = (const float*)d_in[7];
    float* out = (float*)d_out;

    cudaFuncSetAttribute(qkv_gemm_kernel, cudaFuncAttributeMaxDynamicSharedMemorySize, GEMM_SMEM);
    cudaFuncSetAttribute(attn_kernel, cudaFuncAttributeMaxDynamicSharedMemorySize, ATTN_SMEM);

    int total_groups = XGRP + 3 * WGRP;
    preround_kernel<<<total_groups / 256, 256>>>(X, Wq, Wk, Wv);

    dim3 gg(8192 / 128, HH / 128, 3);
    qkv_gemm_kernel<<<gg, 256, GEMM_SMEM>>>(bq, bk, bv);

    dim3 ga(SS / 128, BH);
    attn_kernel<<<ga, 256, ATTN_SMEM>>>(mask, out);
}